// round 7
// baseline (speedup 1.0000x reference)
#include <cuda_runtime.h>

// LSTM seq2seq: B=64, T=512, F=64, H=512, FUT=96 — persistent-kernel design v2.
//  - 2 persistent kernels (encoder pipelined L0+L1; decoder) + software grid barrier.
//  - Weights resident in shared memory; c-state in registers.
//  - 64-k chunks, double-buffered activation staging: ONE __syncthreads per chunk.
//  - Split-k accumulator pairs (P/Q) -> 4+ independent FFMA2 chains, merged with add.rn.f32x2.
//  - Barrier pollers use ld.acquire.gpu (no atomic serialization).

#define BB 64
#define TT 512
#define FF 64
#define HH 512
#define FUT 96
#define BH (BB*HH)          // 32768

#define NBLK 128
#define NTHR 256
#define WSS   514           // padded k-stride (ulonglong2) for K=512 tiles
#define WSS64 66            // padded k-stride for K=64 tiles
#define CHK 64              // k-chunk size
#define HS_PAD 68           // padded floats per staged activation row
#define HSBUF (64*HS_PAD)   // one staging buffer (floats)

// ---------------- device scratch ----------------
__device__ float  g_y0[TT*BB*HH];         // enc L0 h history
__device__ float  g_h1hist[FUT*BB*HH];    // decoder L1 h history
__device__ float  g_zero[BH];
__device__ float  g_c0[BH], g_c1[BH];
__device__ float  g_h1A[BH], g_h1B[BH], g_h0A[BH], g_h0B[BH];

__device__ float4 g_pW_enc_ih0[HH*FF];
__device__ float4 g_pW_enc_hh0[HH*HH];
__device__ float4 g_pW_enc_ih1[HH*HH];
__device__ float4 g_pW_enc_hh1[HH*HH];
__device__ float4 g_pW_dec_ih0[HH*FF];
__device__ float4 g_pW_dec_hh0[HH*HH];
__device__ float4 g_pW_dec_ih1[HH*HH];
__device__ float4 g_pW_dec_hh1[HH*HH];
__device__ float4 g_pW_dec0c[HH*HH];      // combined Wih0 @ fcW
__device__ float4 g_pb_enc0[HH], g_pb_enc1[HH], g_pb_dec0[HH], g_pb_dec1[HH], g_pb_dec0c[HH];

__device__ unsigned g_bcount;
__device__ unsigned g_bgen;

// ---------------- f32x2 helpers ----------------
__device__ __forceinline__ unsigned long long bcast2(float v) {
    unsigned int u = __float_as_uint(v);
    unsigned long long r;
    asm("mov.b64 %0, {%1, %1};" : "=l"(r) : "r"(u));
    return r;
}
__device__ __forceinline__ unsigned long long pack2(float a, float b) {
    unsigned long long r;
    asm("mov.b64 %0, {%1, %2};" : "=l"(r) : "r"(__float_as_uint(a)), "r"(__float_as_uint(b)));
    return r;
}
__device__ __forceinline__ float2 unpack2(unsigned long long v) {
    unsigned int lo, hi;
    asm("mov.b64 {%0, %1}, %2;" : "=r"(lo), "=r"(hi) : "l"(v));
    return make_float2(__uint_as_float(lo), __uint_as_float(hi));
}
__device__ __forceinline__ void ffma2(unsigned long long& d, unsigned long long a, unsigned long long b) {
    asm("fma.rn.f32x2 %0, %1, %2, %0;" : "+l"(d) : "l"(a), "l"(b));
}
__device__ __forceinline__ void fadd2(unsigned long long& d, unsigned long long a) {
    asm("add.rn.f32x2 %0, %0, %1;" : "+l"(d) : "l"(a));
}
__device__ __forceinline__ ulonglong2 merge2(ulonglong2 p, ulonglong2 q) {
    fadd2(p.x, q.x); fadd2(p.y, q.y); return p;
}

// ---------------- grid barrier ----------------
__device__ __forceinline__ void grid_barrier(unsigned target) {
    __syncthreads();
    if (threadIdx.x == 0) {
        __threadfence();
        if (atomicAdd(&g_bcount, 1) == NBLK - 1) {
            atomicExch(&g_bcount, 0);
            __threadfence();
            atomicAdd(&g_bgen, 1);
        } else {
            unsigned v;
            do {
                asm volatile("ld.acquire.gpu.u32 %0, [%1];" : "=r"(v) : "l"(&g_bgen));
            } while (v < target);
        }
        __threadfence();
    }
    __syncthreads();
}

// ---------------- inner dot over a 32-k span ----------------
__device__ __forceinline__ void dot32(ulonglong2& acc, const ulonglong2* __restrict__ w,
                                      const float* __restrict__ hrow) {
#pragma unroll
    for (int kk = 0; kk < 32; kk += 4) {
        float4 hv = *(const float4*)(hrow + kk);
        ulonglong2 w0 = w[kk + 0], w1 = w[kk + 1], w2 = w[kk + 2], w3 = w[kk + 3];
        unsigned long long h0 = bcast2(hv.x), h1 = bcast2(hv.y),
                           h2 = bcast2(hv.z), h3 = bcast2(hv.w);
        ffma2(acc.x, h0, w0.x); ffma2(acc.y, h0, w0.y);
        ffma2(acc.x, h1, w1.x); ffma2(acc.y, h1, w1.y);
        ffma2(acc.x, h2, w2.x); ffma2(acc.y, h2, w2.y);
        ffma2(acc.x, h3, w3.x); ffma2(acc.y, h3, w3.y);
    }
}

// K=512 phase, 64-k chunks, double-buffered staging, 1 sync per chunk.
// Accumulates into (a0p,a0q) with Wa and/or (a1p,a1q) with Wb.
// x: [64][512] row-major in global.
template <bool A0, bool A1>
__device__ __forceinline__ void phase512(
    ulonglong2& a0p, ulonglong2& a0q, ulonglong2& a1p, ulonglong2& a1q,
    const float* __restrict__ x,
    const ulonglong2* __restrict__ Wa, const ulonglong2* __restrict__ Wb,
    float* hs, int tid, int jl, int r)
{
    int rr0 = tid >> 5;          // 0..7
    int kk0 = tid & 31;
    float pf[16];
#pragma unroll
    for (int u = 0; u < 8; u++) {
        pf[u]     = x[(rr0 + u * 8) * HH + kk0];
        pf[u + 8] = x[(rr0 + u * 8) * HH + kk0 + 32];
    }
#pragma unroll 2
    for (int kc = 0; kc < HH; kc += CHK) {
        float* buf = hs + ((kc >> 6) & 1) * HSBUF;
#pragma unroll
        for (int u = 0; u < 8; u++) {
            buf[(rr0 + u * 8) * HS_PAD + kk0]      = pf[u];
            buf[(rr0 + u * 8) * HS_PAD + kk0 + 32] = pf[u + 8];
        }
        __syncthreads();
        if (kc + CHK < HH) {
#pragma unroll
            for (int u = 0; u < 8; u++) {
                pf[u]     = x[(rr0 + u * 8) * HH + kc + CHK + kk0];
                pf[u + 8] = x[(rr0 + u * 8) * HH + kc + CHK + kk0 + 32];
            }
        }
        const float* hrow = buf + r * HS_PAD;
        if (A0) {
            dot32(a0p, Wa + jl * WSS + kc,      hrow);
            dot32(a0q, Wa + jl * WSS + kc + 32, hrow + 32);
        }
        if (A1) {
            dot32(a1p, Wb + jl * WSS + kc,      hrow);
            dot32(a1q, Wb + jl * WSS + kc + 32, hrow + 32);
        }
    }
    // no trailing sync needed: next phase's first write targets buffer 0,
    // whose last reader finished before this phase's final sync.
}

// K=64 phase (input_seq projection). Uses staging buffer 1 (parity-safe).
__device__ __forceinline__ void phase64(
    ulonglong2& ap, ulonglong2& aq,
    const float* __restrict__ x, long xstride,
    const ulonglong2* __restrict__ W, float* hs, int tid, int jl, int r)
{
    int rr0 = tid >> 5;
    int kk0 = tid & 31;
    float* buf = hs + HSBUF;   // buffer 1
#pragma unroll
    for (int u = 0; u < 8; u++) {
        buf[(rr0 + u * 8) * HS_PAD + kk0]      = x[(long)(rr0 + u * 8) * xstride + kk0];
        buf[(rr0 + u * 8) * HS_PAD + kk0 + 32] = x[(long)(rr0 + u * 8) * xstride + kk0 + 32];
    }
    __syncthreads();
    const float* hrow = buf + r * HS_PAD;
    dot32(ap, W + jl * WSS64,      hrow);
    dot32(aq, W + jl * WSS64 + 32, hrow + 32);
}

__device__ __forceinline__ float cellfin(ulonglong2 acc, float& c) {
    float2 vif = unpack2(acc.x);
    float2 vgo = unpack2(acc.y);
    float si = 1.f / (1.f + __expf(-vif.x));
    float sf = 1.f / (1.f + __expf(-vif.y));
    float so = 1.f / (1.f + __expf(-vgo.y));
    float cn = sf * c + si * tanhf(vgo.x);
    c = cn;
    return so * tanhf(cn);
}

// smem: enc = 3 big W + W0x + 2 staging buffers; dec = 4 big W + W0x + 2 buffers
#define ENC_SMEM ((3*4*WSS + 4*WSS64) * 16 + 2*HSBUF*4)
#define DEC_SMEM ((4*4*WSS + 4*WSS64) * 16 + 2*HSBUF*4)

// ---------------- persistent encoder: L0 + L1 software-pipelined ----------------
__global__ void __launch_bounds__(NTHR, 1) enc_kernel(
    const float* __restrict__ in_seq,
    const float4* __restrict__ pW0x, const float4* __restrict__ pW0h,
    const float4* __restrict__ pW1x, const float4* __restrict__ pW1h,
    const float4* __restrict__ pb0, const float4* __restrict__ pb1,
    const float* __restrict__ zerobuf,
    float* __restrict__ y0, float* __restrict__ h1A, float* __restrict__ h1B,
    float* __restrict__ c0out, float* __restrict__ c1out)
{
    extern __shared__ __align__(16) unsigned char smraw[];
    ulonglong2* W0h = (ulonglong2*)smraw;
    ulonglong2* W1x = W0h + 4 * WSS;
    ulonglong2* W1h = W1x + 4 * WSS;
    ulonglong2* W0x = W1h + 4 * WSS;
    float* hs = (float*)(W0x + 4 * WSS64);

    int tid = threadIdx.x, jl = tid & 3, r = tid >> 2;
    int j0 = blockIdx.x * 4, j = j0 + jl;
    int idx = (r << 9) + j;

    {   // load smem-resident weight tiles (once)
        const ulonglong2* g0h = (const ulonglong2*)pW0h + (size_t)j0 * HH;
        const ulonglong2* g1x = (const ulonglong2*)pW1x + (size_t)j0 * HH;
        const ulonglong2* g1h = (const ulonglong2*)pW1h + (size_t)j0 * HH;
#pragma unroll 2
        for (int i = tid; i < 4 * HH; i += NTHR) {
            int jj = i >> 9, kk = i & 511;
            W0h[jj * WSS + kk] = g0h[i];
            W1x[jj * WSS + kk] = g1x[i];
            W1h[jj * WSS + kk] = g1h[i];
        }
        const ulonglong2* g0x = (const ulonglong2*)pW0x + (size_t)j0 * FF;
        if (tid < 4 * FF) {
            int jj = tid >> 6, kk = tid & 63;
            W0x[jj * WSS64 + kk] = g0x[tid];
        }
    }
    float4 b0 = pb0[j], b1 = pb1[j];
    float c0 = 0.f, c1 = 0.f;
    __syncthreads();

    unsigned gen = 0;
    for (int slot = 0; slot <= TT; slot++) {
        bool doL0 = (slot < TT);
        bool doL1 = (slot > 0);
        const float* yprev = (slot == 0) ? zerobuf : (y0 + (size_t)(slot - 1) * BH);

        ulonglong2 a0p, a0q, a1p, a1q;
        a0q.x = a0q.y = a1q.x = a1q.y = 0ULL;
        a0p.x = a0p.y = a1p.x = a1p.y = 0ULL;

        if (doL0) {
            a0p.x = pack2(b0.x, b0.y); a0p.y = pack2(b0.z, b0.w);
            phase64(a0p, a0q, in_seq + (size_t)slot * FF, (long)TT * FF, W0x, hs, tid, jl, r);
        }
        if (doL1) { a1p.x = pack2(b1.x, b1.y); a1p.y = pack2(b1.z, b1.w); }

        if (doL0 && doL1)
            phase512<true, true >(a0p, a0q, a1p, a1q, yprev, W0h, W1x, hs, tid, jl, r);
        else if (doL0)
            phase512<true, false>(a0p, a0q, a1p, a1q, yprev, W0h, W1x, hs, tid, jl, r);
        else
            phase512<false, true>(a0p, a0q, a1p, a1q, yprev, W0h, W1x, hs, tid, jl, r);

        if (doL1) {
            const float* h1p = (slot == 1) ? zerobuf : ((slot & 1) ? h1A : h1B);
            phase512<false, true>(a0p, a0q, a1p, a1q, h1p, W0h, W1h, hs, tid, jl, r);
            ulonglong2 m = merge2(a1p, a1q);
            float* h1o = (slot & 1) ? h1B : h1A;    // slot s -> buf[s&1]
            h1o[idx] = cellfin(m, c1);
        }
        if (doL0) {
            ulonglong2 m = merge2(a0p, a0q);
            y0[(size_t)slot * BH + idx] = cellfin(m, c0);
        }

        gen++;
        grid_barrier(gen);
    }
    c0out[idx] = c0;
    c1out[idx] = c1;
    // final h1 is at slot TT (even) -> h1A
}

// ---------------- persistent decoder ----------------
__global__ void __launch_bounds__(NTHR, 1) dec_kernel(
    const float* __restrict__ in_seq,
    const float4* __restrict__ pWd0x, const float4* __restrict__ pWd0c,
    const float4* __restrict__ pWdh0, const float4* __restrict__ pWdx1,
    const float4* __restrict__ pWdh1,
    const float4* __restrict__ pbD0, const float4* __restrict__ pbD0c,
    const float4* __restrict__ pbD1,
    const float* __restrict__ h0init, const float* __restrict__ h1init,
    const float* __restrict__ c0in, const float* __restrict__ c1in,
    float* __restrict__ h0A, float* __restrict__ h0B, float* __restrict__ h1hist)
{
    extern __shared__ __align__(16) unsigned char smraw[];
    ulonglong2* Wc  = (ulonglong2*)smraw;
    ulonglong2* Wh0 = Wc  + 4 * WSS;
    ulonglong2* Wx1 = Wh0 + 4 * WSS;
    ulonglong2* Wh1 = Wx1 + 4 * WSS;
    ulonglong2* W0x = Wh1 + 4 * WSS;
    float* hs = (float*)(W0x + 4 * WSS64);

    int tid = threadIdx.x, jl = tid & 3, r = tid >> 2;
    int j0 = blockIdx.x * 4, j = j0 + jl;
    int idx = (r << 9) + j;

    {
        const ulonglong2* gc  = (const ulonglong2*)pWd0c + (size_t)j0 * HH;
        const ulonglong2* gh0 = (const ulonglong2*)pWdh0 + (size_t)j0 * HH;
        const ulonglong2* gx1 = (const ulonglong2*)pWdx1 + (size_t)j0 * HH;
        const ulonglong2* gh1 = (const ulonglong2*)pWdh1 + (size_t)j0 * HH;
#pragma unroll 2
        for (int i = tid; i < 4 * HH; i += NTHR) {
            int jj = i >> 9, kk = i & 511;
            Wc[jj * WSS + kk]  = gc[i];
            Wh0[jj * WSS + kk] = gh0[i];
            Wx1[jj * WSS + kk] = gx1[i];
            Wh1[jj * WSS + kk] = gh1[i];
        }
        const ulonglong2* g0x = (const ulonglong2*)pWd0x + (size_t)j0 * FF;
        if (tid < 4 * FF) {
            int jj = tid >> 6, kk = tid & 63;
            W0x[jj * WSS64 + kk] = g0x[tid];
        }
    }
    float4 bd0 = pbD0[j], bd0c = pbD0c[j], bd1 = pbD1[j];
    float c0 = c0in[idx], c1 = c1in[idx];
    __syncthreads();

    unsigned gen = 0;
    const float* h0prev = h0init;
    const float* h1prev = h1init;
    ulonglong2 d0, d1;   // dummies for unused template slots

    for (int t = 0; t < FUT; t++) {
        // ---- cell d0 ----
        ulonglong2 ap, aq;
        aq.x = aq.y = 0ULL;
        if (t == 0) {
            ap.x = pack2(bd0.x, bd0.y); ap.y = pack2(bd0.z, bd0.w);
            phase64(ap, aq, in_seq + (size_t)(TT - 1) * FF, (long)TT * FF, W0x, hs, tid, jl, r);
        } else {
            ap.x = pack2(bd0c.x, bd0c.y); ap.y = pack2(bd0c.z, bd0c.w);
            phase512<true, false>(ap, aq, d0, d1, h1hist + (size_t)(t - 1) * BH, Wc, Wc, hs, tid, jl, r);
        }
        phase512<true, false>(ap, aq, d0, d1, h0prev, Wh0, Wh0, hs, tid, jl, r);
        {
            ulonglong2 m = merge2(ap, aq);
            float* h0out = (t & 1) ? h0B : h0A;
            h0out[idx] = cellfin(m, c0);
            gen++; grid_barrier(gen);

            // ---- cell d1 ----
            ulonglong2 bp, bq;
            bq.x = bq.y = 0ULL;
            bp.x = pack2(bd1.x, bd1.y); bp.y = pack2(bd1.z, bd1.w);
            phase512<true, false>(bp, bq, d0, d1, h0out, Wx1, Wx1, hs, tid, jl, r);
            phase512<true, false>(bp, bq, d0, d1, h1prev, Wh1, Wh1, hs, tid, jl, r);
            ulonglong2 m2 = merge2(bp, bq);
            h1hist[(size_t)t * BH + idx] = cellfin(m2, c1);
            gen++; grid_barrier(gen);

            h0prev = h0out;
            h1prev = h1hist + (size_t)t * BH;
        }
    }
}

// ---------------- packing / misc kernels ----------------
__global__ void pack_w_kernel(const float* __restrict__ W, float4* __restrict__ P, int Kin) {
    int idx = blockIdx.x * 256 + threadIdx.x;
    if (idx >= HH * Kin) return;
    int j = idx / Kin, k = idx - j * Kin;
    P[idx] = make_float4(W[j * Kin + k], W[(j + 512) * Kin + k],
                         W[(j + 1024) * Kin + k], W[(j + 1536) * Kin + k]);
}
__global__ void pack_b_kernel(const float* __restrict__ bih, const float* __restrict__ bhh,
                              float4* __restrict__ pb) {
    int j = blockIdx.x * 256 + threadIdx.x;
    if (j >= HH) return;
    pb[j] = make_float4(bih[j] + bhh[j], bih[j + 512] + bhh[j + 512],
                        bih[j + 1024] + bhh[j + 1024], bih[j + 1536] + bhh[j + 1536]);
}
__global__ void combine_dec0_kernel(const float4* __restrict__ pWih0, const float* __restrict__ fcW,
                                    const float4* __restrict__ pb0, const float* __restrict__ fcb,
                                    float4* __restrict__ Pc, float4* __restrict__ pbc) {
    int idx = blockIdx.x * 256 + threadIdx.x;
    if (idx >= HH * HH) return;
    int j = idx >> 9, hh = idx & 511;
    float4 acc = make_float4(0.f, 0.f, 0.f, 0.f);
#pragma unroll 8
    for (int n = 0; n < FF; n++) {
        float4 w = pWih0[(j << 6) + n];
        float f = fcW[(n << 9) + hh];
        acc.x += w.x * f; acc.y += w.y * f; acc.z += w.z * f; acc.w += w.w * f;
    }
    Pc[idx] = acc;
    if (hh == 0) {
        float4 bb = pb0[j];
#pragma unroll 8
        for (int n = 0; n < FF; n++) {
            float4 w = pWih0[(j << 6) + n];
            float f = fcb[n];
            bb.x += w.x * f; bb.y += w.y * f; bb.z += w.z * f; bb.w += w.w * f;
        }
        pbc[j] = bb;
    }
}
__global__ void init_kernel(float* zerobuf) {
    int i = blockIdx.x * 256 + threadIdx.x;
    if (i < BH) zerobuf[i] = 0.f;
    if (i == 0) { g_bcount = 0; g_bgen = 0; }
}
__global__ void reset_bar_kernel() {
    g_bcount = 0; g_bgen = 0;
}
// out[b][t][n] = fc_b[n] + sum_h h1hist[t][b][h] * fcW[n][h]
__global__ void final_fc_kernel(const float* __restrict__ h1hist, const float* __restrict__ fcW,
                                const float* __restrict__ fcb, float* __restrict__ out) {
    int t = blockIdx.y;
    int l = blockIdx.x * 256 + threadIdx.x;
    int b = l >> 6, n = l & 63;
    const float4* h4 = (const float4*)(h1hist + ((size_t)t * BB + b) * HH);
    const float4* w4 = (const float4*)(fcW + (size_t)n * HH);
    float acc = fcb[n];
#pragma unroll 8
    for (int k = 0; k < HH / 4; k++) {
        float4 a = h4[k], w = w4[k];
        acc += a.x * w.x + a.y * w.y + a.z * w.z + a.w * w.w;
    }
    out[((size_t)b * FUT + t) * FF + n] = acc;
}

// ---------------- host ----------------
extern "C" void kernel_launch(void* const* d_in, const int* in_sizes, int n_in,
                              void* d_out, int out_size) {
    const float* in_seq = (const float*)d_in[0];
    const float* eWih0  = (const float*)d_in[1];
    const float* eWhh0  = (const float*)d_in[2];
    const float* ebih0  = (const float*)d_in[3];
    const float* ebhh0  = (const float*)d_in[4];
    const float* eWih1  = (const float*)d_in[5];
    const float* eWhh1  = (const float*)d_in[6];
    const float* ebih1  = (const float*)d_in[7];
    const float* ebhh1  = (const float*)d_in[8];
    const float* dWih0  = (const float*)d_in[9];
    const float* dWhh0  = (const float*)d_in[10];
    const float* dbih0  = (const float*)d_in[11];
    const float* dbhh0  = (const float*)d_in[12];
    const float* dWih1  = (const float*)d_in[13];
    const float* dWhh1  = (const float*)d_in[14];
    const float* dbih1  = (const float*)d_in[15];
    const float* dbhh1  = (const float*)d_in[16];
    const float* fcW    = (const float*)d_in[17];
    const float* fcb    = (const float*)d_in[18];
    float* out = (float*)d_out;

    static int s_attr_done = 0;
    if (!s_attr_done) {
        cudaFuncSetAttribute(enc_kernel, cudaFuncAttributeMaxDynamicSharedMemorySize, ENC_SMEM);
        cudaFuncSetAttribute(dec_kernel, cudaFuncAttributeMaxDynamicSharedMemorySize, DEC_SMEM);
        s_attr_done = 1;
    }

    float4 *pWeih0, *pWehh0, *pWeih1, *pWehh1, *pWdih0, *pWdhh0, *pWdih1, *pWdhh1, *pWd0c;
    float4 *pbE0, *pbE1, *pbD0, *pbD1, *pbD0c;
    float *y0, *h1hist, *zerobuf, *c0, *c1, *h1A, *h1B, *h0A, *h0B;
    cudaGetSymbolAddress((void**)&y0,      g_y0);
    cudaGetSymbolAddress((void**)&h1hist,  g_h1hist);
    cudaGetSymbolAddress((void**)&zerobuf, g_zero);
    cudaGetSymbolAddress((void**)&c0,      g_c0);
    cudaGetSymbolAddress((void**)&c1,      g_c1);
    cudaGetSymbolAddress((void**)&h1A,     g_h1A);
    cudaGetSymbolAddress((void**)&h1B,     g_h1B);
    cudaGetSymbolAddress((void**)&h0A,     g_h0A);
    cudaGetSymbolAddress((void**)&h0B,     g_h0B);
    cudaGetSymbolAddress((void**)&pWeih0,  g_pW_enc_ih0);
    cudaGetSymbolAddress((void**)&pWehh0,  g_pW_enc_hh0);
    cudaGetSymbolAddress((void**)&pWeih1,  g_pW_enc_ih1);
    cudaGetSymbolAddress((void**)&pWehh1,  g_pW_enc_hh1);
    cudaGetSymbolAddress((void**)&pWdih0,  g_pW_dec_ih0);
    cudaGetSymbolAddress((void**)&pWdhh0,  g_pW_dec_hh0);
    cudaGetSymbolAddress((void**)&pWdih1,  g_pW_dec_ih1);
    cudaGetSymbolAddress((void**)&pWdhh1,  g_pW_dec_hh1);
    cudaGetSymbolAddress((void**)&pWd0c,   g_pW_dec0c);
    cudaGetSymbolAddress((void**)&pbE0,    g_pb_enc0);
    cudaGetSymbolAddress((void**)&pbE1,    g_pb_enc1);
    cudaGetSymbolAddress((void**)&pbD0,    g_pb_dec0);
    cudaGetSymbolAddress((void**)&pbD1,    g_pb_dec1);
    cudaGetSymbolAddress((void**)&pbD0c,   g_pb_dec0c);

    // --- pack weights/biases + init ---
    pack_w_kernel<<<(HH * FF + 255) / 256, 256>>>(eWih0, pWeih0, FF);
    pack_w_kernel<<<(HH * HH + 255) / 256, 256>>>(eWhh0, pWehh0, HH);
    pack_w_kernel<<<(HH * HH + 255) / 256, 256>>>(eWih1, pWeih1, HH);
    pack_w_kernel<<<(HH * HH + 255) / 256, 256>>>(eWhh1, pWehh1, HH);
    pack_w_kernel<<<(HH * FF + 255) / 256, 256>>>(dWih0, pWdih0, FF);
    pack_w_kernel<<<(HH * HH + 255) / 256, 256>>>(dWhh0, pWdhh0, HH);
    pack_w_kernel<<<(HH * HH + 255) / 256, 256>>>(dWih1, pWdih1, HH);
    pack_w_kernel<<<(HH * HH + 255) / 256, 256>>>(dWhh1, pWdhh1, HH);
    pack_b_kernel<<<2, 256>>>(ebih0, ebhh0, pbE0);
    pack_b_kernel<<<2, 256>>>(ebih1, ebhh1, pbE1);
    pack_b_kernel<<<2, 256>>>(dbih0, dbhh0, pbD0);
    pack_b_kernel<<<2, 256>>>(dbih1, dbhh1, pbD1);
    combine_dec0_kernel<<<(HH * HH + 255) / 256, 256>>>(pWdih0, fcW, pbD0, fcb, pWd0c, pbD0c);
    init_kernel<<<(BH + 255) / 256, 256>>>(zerobuf);

    // --- persistent encoder (513 slots, pipelined L0+L1) ---
    enc_kernel<<<NBLK, NTHR, ENC_SMEM>>>(
        in_seq, pWeih0, pWehh0, pWeih1, pWehh1, pbE0, pbE1,
        zerobuf, y0, h1A, h1B, c0, c1);

    reset_bar_kernel<<<1, 1>>>();

    // --- persistent decoder (96 steps x 2 cells) ---
    dec_kernel<<<NBLK, NTHR, DEC_SMEM>>>(
        in_seq, pWdih0, pWd0c, pWdhh0, pWdih1, pWdhh1,
        pbD0, pbD0c, pbD1,
        y0 + (size_t)(TT - 1) * BH, /* enc L0 final h */
        h1A,                        /* enc L1 final h (slot TT even) */
        c0, c1, h0A, h0B, h1hist);

    // --- batched final FC ---
    {
        dim3 grid(16, FUT);
        final_fc_kernel<<<grid, 256>>>(h1hist, fcW, fcb, out);
    }
}

// round 8
// speedup vs baseline: 1.6132x; 1.6132x over previous
#include <cuda_runtime.h>

// LSTM seq2seq: B=64, T=512, F=64, H=512, FUT=96 — persistent v3.
//  - 2 rows per thread (128 thr/block): halves LDS warp-instructions per FFMA2.
//  - float4 staging (LDG.128/STS.128), double-buffered, 1 sync per 64-k chunk.
//  - Weights resident in smem; c-state in registers; software grid barrier.
//  - Launches ordered so ncu (-s 5 -c 1) captures enc_kernel.

#define BB 64
#define TT 512
#define FF 64
#define HH 512
#define FUT 96
#define BH (BB*HH)          // 32768

#define NBLK 128
#define NTHR 128
#define WSS   514           // padded k-stride (ulonglong2) for K=512 tiles
#define WSS64 66            // padded k-stride for K=64 tiles
#define HSP 68              // padded floats per staged activation row (17 float4)
#define HSBUFF (64*HSP)     // one staging buffer (floats)

// ---------------- device scratch ----------------
__device__ float  g_y0[TT*BB*HH];
__device__ float  g_h1hist[FUT*BB*HH];
__device__ float  g_zero[BH];
__device__ float  g_c0[BH], g_c1[BH];
__device__ float  g_h1A[BH], g_h1B[BH], g_h0A[BH], g_h0B[BH];

__device__ float4 g_pW_enc_ih0[HH*FF];
__device__ float4 g_pW_enc_hh0[HH*HH];
__device__ float4 g_pW_enc_ih1[HH*HH];
__device__ float4 g_pW_enc_hh1[HH*HH];
__device__ float4 g_pW_dec_ih0[HH*FF];
__device__ float4 g_pW_dec_hh0[HH*HH];
__device__ float4 g_pW_dec_ih1[HH*HH];
__device__ float4 g_pW_dec_hh1[HH*HH];
__device__ float4 g_pW_dec0c[HH*HH];
__device__ float4 g_pb_enc0[HH], g_pb_enc1[HH], g_pb_dec0[HH], g_pb_dec1[HH], g_pb_dec0c[HH];

__device__ unsigned g_bcount;
__device__ unsigned g_bgen;

// ---------------- f32x2 helpers ----------------
__device__ __forceinline__ unsigned long long bcast2(float v) {
    unsigned int u = __float_as_uint(v);
    unsigned long long r;
    asm("mov.b64 %0, {%1, %1};" : "=l"(r) : "r"(u));
    return r;
}
__device__ __forceinline__ unsigned long long pack2(float a, float b) {
    unsigned long long r;
    asm("mov.b64 %0, {%1, %2};" : "=l"(r) : "r"(__float_as_uint(a)), "r"(__float_as_uint(b)));
    return r;
}
__device__ __forceinline__ float2 unpack2(unsigned long long v) {
    unsigned int lo, hi;
    asm("mov.b64 {%0, %1}, %2;" : "=r"(lo), "=r"(hi) : "l"(v));
    return make_float2(__uint_as_float(lo), __uint_as_float(hi));
}
__device__ __forceinline__ void ffma2(unsigned long long& d, unsigned long long a, unsigned long long b) {
    asm("fma.rn.f32x2 %0, %1, %2, %0;" : "+l"(d) : "l"(a), "l"(b));
}
__device__ __forceinline__ void fadd2(unsigned long long& d, unsigned long long a) {
    asm("add.rn.f32x2 %0, %0, %1;" : "+l"(d) : "l"(a));
}
__device__ __forceinline__ ulonglong2 merge2(ulonglong2 p, ulonglong2 q) {
    fadd2(p.x, q.x); fadd2(p.y, q.y); return p;
}

// ---------------- grid barrier ----------------
__device__ __forceinline__ void grid_barrier(unsigned target) {
    __syncthreads();
    if (threadIdx.x == 0) {
        __threadfence();
        if (atomicAdd(&g_bcount, 1) == NBLK - 1) {
            atomicExch(&g_bcount, 0);
            __threadfence();
            atomicAdd(&g_bgen, 1);
        } else {
            unsigned v;
            do {
                asm volatile("ld.acquire.gpu.u32 %0, [%1];" : "=r"(v) : "l"(&g_bgen));
            } while (v < target);
        }
        __threadfence();
    }
    __syncthreads();
}

// ---------------- chunk compute (64 k), 2 rows per thread ----------------
// Single matrix: accumulate rows r0->(p0,q0), r1->(p1,q1). Chain reuse distance 8.
__device__ __forceinline__ void chunk_single(
    ulonglong2& p0, ulonglong2& q0, ulonglong2& p1, ulonglong2& q1,
    const ulonglong2* __restrict__ w,
    const float* __restrict__ h0, const float* __restrict__ h1)
{
#pragma unroll
    for (int kk = 0; kk < 64; kk += 4) {
        float4 a = *(const float4*)(h0 + kk);
        float4 b = *(const float4*)(h1 + kk);
        ulonglong2 w0 = w[kk], w1 = w[kk + 1], w2 = w[kk + 2], w3 = w[kk + 3];
        unsigned long long ax = bcast2(a.x), ay = bcast2(a.y), az = bcast2(a.z), aw = bcast2(a.w);
        unsigned long long bx = bcast2(b.x), by = bcast2(b.y), bz = bcast2(b.z), bw = bcast2(b.w);
        ffma2(p0.x, ax, w0.x); ffma2(p0.y, ax, w0.y);
        ffma2(p1.x, bx, w0.x); ffma2(p1.y, bx, w0.y);
        ffma2(q0.x, ay, w1.x); ffma2(q0.y, ay, w1.y);
        ffma2(q1.x, by, w1.x); ffma2(q1.y, by, w1.y);
        ffma2(p0.x, az, w2.x); ffma2(p0.y, az, w2.y);
        ffma2(p1.x, bz, w2.x); ffma2(p1.y, bz, w2.y);
        ffma2(q0.x, aw, w3.x); ffma2(q0.y, aw, w3.y);
        ffma2(q1.x, bw, w3.x); ffma2(q1.y, bw, w3.y);
    }
}

// Dual matrix (same activations): A (rows a0,a1) with wa; B (rows b0,b1) with wb.
__device__ __forceinline__ void chunk_dual(
    ulonglong2& a0, ulonglong2& a1, ulonglong2& b0, ulonglong2& b1,
    const ulonglong2* __restrict__ wa, const ulonglong2* __restrict__ wb,
    const float* __restrict__ h0, const float* __restrict__ h1)
{
#pragma unroll
    for (int kk = 0; kk < 64; kk += 2) {
        float2 a = *(const float2*)(h0 + kk);
        float2 b = *(const float2*)(h1 + kk);
        ulonglong2 wa0 = wa[kk], wa1 = wa[kk + 1];
        ulonglong2 wb0 = wb[kk], wb1 = wb[kk + 1];
        unsigned long long ax = bcast2(a.x), ay = bcast2(a.y);
        unsigned long long bx = bcast2(b.x), by = bcast2(b.y);
        ffma2(a0.x, ax, wa0.x); ffma2(a0.y, ax, wa0.y);
        ffma2(a1.x, bx, wa0.x); ffma2(a1.y, bx, wa0.y);
        ffma2(b0.x, ax, wb0.x); ffma2(b0.y, ax, wb0.y);
        ffma2(b1.x, bx, wb0.x); ffma2(b1.y, bx, wb0.y);
        ffma2(a0.x, ay, wa1.x); ffma2(a0.y, ay, wa1.y);
        ffma2(a1.x, by, wa1.x); ffma2(a1.y, by, wa1.y);
        ffma2(b0.x, ay, wb1.x); ffma2(b0.y, ay, wb1.y);
        ffma2(b1.x, by, wb1.x); ffma2(b1.y, by, wb1.y);
    }
}

// ---------------- staged K=512 phases ----------------
// x: [64][512] row-major. Staging: 8 float4 per thread per chunk, double-buffered.
// Thread maps: rbase = tid>>4 (0..7), c4 = tid&15. Rows rbase + u*8.
__device__ __forceinline__ void phase512_single(
    ulonglong2& p0, ulonglong2& q0, ulonglong2& p1, ulonglong2& q1,
    const float* __restrict__ x, const ulonglong2* __restrict__ W,
    float* hs, int tid, int jl, int rh)
{
    const float4* x4 = (const float4*)x;
    int rbase = tid >> 4, c4 = tid & 15;
    float4 pf[8];
#pragma unroll
    for (int u = 0; u < 8; u++) pf[u] = x4[(rbase + u * 8) * 128 + c4];
#pragma unroll 1
    for (int kc = 0; kc < HH; kc += 64) {
        float* buf = hs + ((kc >> 6) & 1) * HSBUFF;
        float4* buf4 = (float4*)buf;
#pragma unroll
        for (int u = 0; u < 8; u++) buf4[(rbase + u * 8) * 17 + c4] = pf[u];
        __syncthreads();
        if (kc + 64 < HH) {
            int k4 = (kc + 64) >> 2;
#pragma unroll
            for (int u = 0; u < 8; u++) pf[u] = x4[(rbase + u * 8) * 128 + k4 + c4];
        }
        chunk_single(p0, q0, p1, q1, W + jl * WSS + kc,
                     buf + rh * HSP, buf + (rh + 32) * HSP);
    }
}

__device__ __forceinline__ void phase512_dual(
    ulonglong2& a0, ulonglong2& a1, ulonglong2& b0, ulonglong2& b1,
    const float* __restrict__ x,
    const ulonglong2* __restrict__ Wa, const ulonglong2* __restrict__ Wb,
    float* hs, int tid, int jl, int rh)
{
    const float4* x4 = (const float4*)x;
    int rbase = tid >> 4, c4 = tid & 15;
    float4 pf[8];
#pragma unroll
    for (int u = 0; u < 8; u++) pf[u] = x4[(rbase + u * 8) * 128 + c4];
#pragma unroll 1
    for (int kc = 0; kc < HH; kc += 64) {
        float* buf = hs + ((kc >> 6) & 1) * HSBUFF;
        float4* buf4 = (float4*)buf;
#pragma unroll
        for (int u = 0; u < 8; u++) buf4[(rbase + u * 8) * 17 + c4] = pf[u];
        __syncthreads();
        if (kc + 64 < HH) {
            int k4 = (kc + 64) >> 2;
#pragma unroll
            for (int u = 0; u < 8; u++) pf[u] = x4[(rbase + u * 8) * 128 + k4 + c4];
        }
        chunk_dual(a0, a1, b0, b1, Wa + jl * WSS + kc, Wb + jl * WSS + kc,
                   buf + rh * HSP, buf + (rh + 32) * HSP);
    }
}

// K=64 phase (input projection). Uses staging buffer 1 (parity-safe vs phase512).
__device__ __forceinline__ void phase64_single(
    ulonglong2& p0, ulonglong2& q0, ulonglong2& p1, ulonglong2& q1,
    const float* __restrict__ x, long xstride,
    const ulonglong2* __restrict__ W, float* hs, int tid, int jl, int rh)
{
    const float4* x4 = (const float4*)x;
    long xs4 = xstride >> 2;
    int rbase = tid >> 4, c4 = tid & 15;
    float* buf = hs + HSBUFF;
    float4* buf4 = (float4*)buf;
#pragma unroll
    for (int u = 0; u < 8; u++)
        buf4[(rbase + u * 8) * 17 + c4] = x4[(long)(rbase + u * 8) * xs4 + c4];
    __syncthreads();
    chunk_single(p0, q0, p1, q1, W + jl * WSS64,
                 buf + rh * HSP, buf + (rh + 32) * HSP);
}

__device__ __forceinline__ float cellfin(ulonglong2 acc, float& c) {
    float2 vif = unpack2(acc.x);
    float2 vgo = unpack2(acc.y);
    float si = 1.f / (1.f + __expf(-vif.x));
    float sf = 1.f / (1.f + __expf(-vif.y));
    float so = 1.f / (1.f + __expf(-vgo.y));
    float cn = sf * c + si * tanhf(vgo.x);
    c = cn;
    return so * tanhf(cn);
}

#define ENC_SMEM ((3*4*WSS + 4*WSS64) * 16 + 2*HSBUFF*4)
#define DEC_SMEM ((4*4*WSS + 4*WSS64) * 16 + 2*HSBUFF*4)

// ---------------- persistent encoder: L0 + L1 software-pipelined ----------------
__global__ void __launch_bounds__(NTHR, 1) enc_kernel(
    const float* __restrict__ in_seq,
    const float4* __restrict__ pW0x, const float4* __restrict__ pW0h,
    const float4* __restrict__ pW1x, const float4* __restrict__ pW1h,
    const float4* __restrict__ pb0, const float4* __restrict__ pb1,
    const float* __restrict__ zerobuf,
    float* __restrict__ y0, float* __restrict__ h1A, float* __restrict__ h1B,
    float* __restrict__ c0out, float* __restrict__ c1out)
{
    extern __shared__ __align__(16) unsigned char smraw[];
    ulonglong2* W0h = (ulonglong2*)smraw;
    ulonglong2* W1x = W0h + 4 * WSS;
    ulonglong2* W1h = W1x + 4 * WSS;
    ulonglong2* W0x = W1h + 4 * WSS;
    float* hs = (float*)(W0x + 4 * WSS64);

    int tid = threadIdx.x, jl = tid & 3, rh = tid >> 2;   // rh 0..31
    int j0 = blockIdx.x * 4, j = j0 + jl;
    int idx0 = (rh << 9) + j;
    int idx1 = ((rh + 32) << 9) + j;

    {   // load weight tiles (once)
        const ulonglong2* g0h = (const ulonglong2*)pW0h + (size_t)j0 * HH;
        const ulonglong2* g1x = (const ulonglong2*)pW1x + (size_t)j0 * HH;
        const ulonglong2* g1h = (const ulonglong2*)pW1h + (size_t)j0 * HH;
#pragma unroll 2
        for (int i = tid; i < 4 * HH; i += NTHR) {
            int jj = i >> 9, kk = i & 511;
            W0h[jj * WSS + kk] = g0h[i];
            W1x[jj * WSS + kk] = g1x[i];
            W1h[jj * WSS + kk] = g1h[i];
        }
        const ulonglong2* g0x = (const ulonglong2*)pW0x + (size_t)j0 * FF;
#pragma unroll
        for (int i = tid; i < 4 * FF; i += NTHR) {
            int jj = i >> 6, kk = i & 63;
            W0x[jj * WSS64 + kk] = g0x[i];
        }
    }
    float4 b0 = pb0[j], b1 = pb1[j];
    unsigned long long b0x = pack2(b0.x, b0.y), b0y = pack2(b0.z, b0.w);
    unsigned long long b1x = pack2(b1.x, b1.y), b1y = pack2(b1.z, b1.w);
    float c0a = 0.f, c0b = 0.f, c1a = 0.f, c1b = 0.f;
    __syncthreads();

    unsigned gen = 0;
    for (int slot = 0; slot <= TT; slot++) {
        bool doL0 = (slot < TT);
        bool doL1 = (slot > 0);
        const float* yprev = (slot == 0) ? zerobuf : (y0 + (size_t)(slot - 1) * BH);

        ulonglong2 P00, Q00, P01, Q01, P10, Q10, P11, Q11;
        Q00.x = Q00.y = Q01.x = Q01.y = 0ULL;
        Q10.x = Q10.y = Q11.x = Q11.y = 0ULL;
        P00.x = b0x; P00.y = b0y; P01.x = b0x; P01.y = b0y;
        P10.x = b1x; P10.y = b1y; P11.x = b1x; P11.y = b1y;

        if (doL0)
            phase64_single(P00, Q00, P01, Q01, in_seq + (size_t)slot * FF,
                           (long)TT * FF, W0x, hs, tid, jl, rh);

        if (doL0 && doL1)
            phase512_dual(P00, P01, P10, P11, yprev, W0h, W1x, hs, tid, jl, rh);
        else if (doL0)
            phase512_single(P00, Q00, P01, Q01, yprev, W0h, hs, tid, jl, rh);
        else
            phase512_single(P10, Q10, P11, Q11, yprev, W1x, hs, tid, jl, rh);

        if (doL1) {
            const float* h1p = (slot == 1) ? zerobuf : ((slot & 1) ? h1A : h1B);
            phase512_single(P10, Q10, P11, Q11, h1p, W1h, hs, tid, jl, rh);
            float* h1o = (slot & 1) ? h1B : h1A;
            h1o[idx0] = cellfin(merge2(P10, Q10), c1a);
            h1o[idx1] = cellfin(merge2(P11, Q11), c1b);
        }
        if (doL0) {
            float* yo = y0 + (size_t)slot * BH;
            yo[idx0] = cellfin(merge2(P00, Q00), c0a);
            yo[idx1] = cellfin(merge2(P01, Q01), c0b);
        }

        gen++;
        grid_barrier(gen);
    }
    c0out[idx0] = c0a; c0out[idx1] = c0b;
    c1out[idx0] = c1a; c1out[idx1] = c1b;
    // final h1 at slot TT (even) -> h1A
}

// ---------------- persistent decoder ----------------
__global__ void __launch_bounds__(NTHR, 1) dec_kernel(
    const float* __restrict__ in_seq,
    const float4* __restrict__ pWd0x, const float4* __restrict__ pWd0c,
    const float4* __restrict__ pWdh0, const float4* __restrict__ pWdx1,
    const float4* __restrict__ pWdh1,
    const float4* __restrict__ pbD0, const float4* __restrict__ pbD0c,
    const float4* __restrict__ pbD1,
    const float* __restrict__ h0init, const float* __restrict__ h1init,
    const float* __restrict__ c0in, const float* __restrict__ c1in,
    float* __restrict__ h0A, float* __restrict__ h0B, float* __restrict__ h1hist)
{
    extern __shared__ __align__(16) unsigned char smraw[];
    ulonglong2* Wc  = (ulonglong2*)smraw;
    ulonglong2* Wh0 = Wc  + 4 * WSS;
    ulonglong2* Wx1 = Wh0 + 4 * WSS;
    ulonglong2* Wh1 = Wx1 + 4 * WSS;
    ulonglong2* W0x = Wh1 + 4 * WSS;
    float* hs = (float*)(W0x + 4 * WSS64);

    int tid = threadIdx.x, jl = tid & 3, rh = tid >> 2;
    int j0 = blockIdx.x * 4, j = j0 + jl;
    int idx0 = (rh << 9) + j;
    int idx1 = ((rh + 32) << 9) + j;

    {
        const ulonglong2* gc  = (const ulonglong2*)pWd0c + (size_t)j0 * HH;
        const ulonglong2* gh0 = (const ulonglong2*)pWdh0 + (size_t)j0 * HH;
        const ulonglong2* gx1 = (const ulonglong2*)pWdx1 + (size_t)j0 * HH;
        const ulonglong2* gh1 = (const ulonglong2*)pWdh1 + (size_t)j0 * HH;
#pragma unroll 2
        for (int i = tid; i < 4 * HH; i += NTHR) {
            int jj = i >> 9, kk = i & 511;
            Wc[jj * WSS + kk]  = gc[i];
            Wh0[jj * WSS + kk] = gh0[i];
            Wx1[jj * WSS + kk] = gx1[i];
            Wh1[jj * WSS + kk] = gh1[i];
        }
        const ulonglong2* g0x = (const ulonglong2*)pWd0x + (size_t)j0 * FF;
#pragma unroll
        for (int i = tid; i < 4 * FF; i += NTHR) {
            int jj = i >> 6, kk = i & 63;
            W0x[jj * WSS64 + kk] = g0x[i];
        }
    }
    float4 bd0 = pbD0[j], bd0c = pbD0c[j], bd1 = pbD1[j];
    float c0a = c0in[idx0], c0b = c0in[idx1];
    float c1a = c1in[idx0], c1b = c1in[idx1];
    __syncthreads();

    unsigned gen = 0;
    const float* h0prev = h0init;
    const float* h1prev = h1init;

    for (int t = 0; t < FUT; t++) {
        // ---- cell d0 ----
        ulonglong2 P0, Q0, P1, Q1;
        Q0.x = Q0.y = Q1.x = Q1.y = 0ULL;
        if (t == 0) {
            P0.x = pack2(bd0.x, bd0.y); P0.y = pack2(bd0.z, bd0.w);
            P1 = P0;
            phase64_single(P0, Q0, P1, Q1, in_seq + (size_t)(TT - 1) * FF,
                           (long)TT * FF, W0x, hs, tid, jl, rh);
        } else {
            P0.x = pack2(bd0c.x, bd0c.y); P0.y = pack2(bd0c.z, bd0c.w);
            P1 = P0;
            phase512_single(P0, Q0, P1, Q1, h1hist + (size_t)(t - 1) * BH, Wc,
                            hs, tid, jl, rh);
        }
        phase512_single(P0, Q0, P1, Q1, h0prev, Wh0, hs, tid, jl, rh);
        float* h0out = (t & 1) ? h0B : h0A;
        h0out[idx0] = cellfin(merge2(P0, Q0), c0a);
        h0out[idx1] = cellfin(merge2(P1, Q1), c0b);
        gen++; grid_barrier(gen);

        // ---- cell d1 ----
        ulonglong2 R0, S0, R1, S1;
        S0.x = S0.y = S1.x = S1.y = 0ULL;
        R0.x = pack2(bd1.x, bd1.y); R0.y = pack2(bd1.z, bd1.w);
        R1 = R0;
        phase512_single(R0, S0, R1, S1, h0out, Wx1, hs, tid, jl, rh);
        phase512_single(R0, S0, R1, S1, h1prev, Wh1, hs, tid, jl, rh);
        float* h1o = h1hist + (size_t)t * BH;
        h1o[idx0] = cellfin(merge2(R0, S0), c1a);
        h1o[idx1] = cellfin(merge2(R1, S1), c1b);
        gen++; grid_barrier(gen);

        h0prev = h0out;
        h1prev = h1o;
    }
}

// ---------------- setup kernels (fused so enc is launch index 5) ----------------
__global__ void pack_all_kernel(
    const float* __restrict__ s0, const float* __restrict__ s1,
    const float* __restrict__ s2, const float* __restrict__ s3,
    const float* __restrict__ s4, const float* __restrict__ s5,
    const float* __restrict__ s6, const float* __restrict__ s7,
    float4* __restrict__ d0, float4* __restrict__ d1,
    float4* __restrict__ d2, float4* __restrict__ d3,
    float4* __restrict__ d4, float4* __restrict__ d5,
    float4* __restrict__ d6, float4* __restrict__ d7,
    const float* __restrict__ bi0, const float* __restrict__ bh0,
    const float* __restrict__ bi1, const float* __restrict__ bh1,
    const float* __restrict__ bi2, const float* __restrict__ bh2,
    const float* __restrict__ bi3, const float* __restrict__ bh3,
    float4* __restrict__ pb0, float4* __restrict__ pb1,
    float4* __restrict__ pb2, float4* __restrict__ pb3)
{
    int m = blockIdx.y;
    int idx = blockIdx.x * 256 + threadIdx.x;
    if (m < 8) {
        const float* S; float4* D; int Kin;
        switch (m) {
            case 0: S = s0; D = d0; Kin = FF; break;
            case 1: S = s1; D = d1; Kin = HH; break;
            case 2: S = s2; D = d2; Kin = HH; break;
            case 3: S = s3; D = d3; Kin = HH; break;
            case 4: S = s4; D = d4; Kin = FF; break;
            case 5: S = s5; D = d5; Kin = HH; break;
            case 6: S = s6; D = d6; Kin = HH; break;
            default: S = s7; D = d7; Kin = HH; break;
        }
        if (idx >= HH * Kin) return;
        int jj = idx / Kin, k = idx - jj * Kin;
        D[idx] = make_float4(S[jj * Kin + k], S[(jj + 512) * Kin + k],
                             S[(jj + 1024) * Kin + k], S[(jj + 1536) * Kin + k]);
    } else {
        if (idx >= 4 * HH) return;
        int which = idx >> 9, jj = idx & 511;
        const float* A; const float* Bb; float4* P;
        switch (which) {
            case 0: A = bi0; Bb = bh0; P = pb0; break;
            case 1: A = bi1; Bb = bh1; P = pb1; break;
            case 2: A = bi2; Bb = bh2; P = pb2; break;
            default: A = bi3; Bb = bh3; P = pb3; break;
        }
        P[jj] = make_float4(A[jj] + Bb[jj], A[jj + 512] + Bb[jj + 512],
                            A[jj + 1024] + Bb[jj + 1024], A[jj + 1536] + Bb[jj + 1536]);
    }
}

__global__ void combine_dec0_kernel(const float4* __restrict__ pWih0, const float* __restrict__ fcW,
                                    const float4* __restrict__ pb0, const float* __restrict__ fcb,
                                    float4* __restrict__ Pc, float4* __restrict__ pbc) {
    int idx = blockIdx.x * 256 + threadIdx.x;
    if (idx >= HH * HH) return;
    int jj = idx >> 9, hh = idx & 511;
    float4 acc = make_float4(0.f, 0.f, 0.f, 0.f);
#pragma unroll 8
    for (int n = 0; n < FF; n++) {
        float4 w = pWih0[(jj << 6) + n];
        float f = fcW[(n << 9) + hh];
        acc.x += w.x * f; acc.y += w.y * f; acc.z += w.z * f; acc.w += w.w * f;
    }
    Pc[idx] = acc;
    if (hh == 0) {
        float4 bb = pb0[jj];
#pragma unroll 8
        for (int n = 0; n < FF; n++) {
            float4 w = pWih0[(jj << 6) + n];
            float f = fcb[n];
            bb.x += w.x * f; bb.y += w.y * f; bb.z += w.z * f; bb.w += w.w * f;
        }
        pbc[jj] = bb;
    }
}
__global__ void init_kernel(float* zerobuf) {
    int i = blockIdx.x * 256 + threadIdx.x;
    if (i < BH) zerobuf[i] = 0.f;
    if (i == 0) { g_bcount = 0; g_bgen = 0; }
}
__global__ void nop_kernel() {}
__global__ void reset_bar_kernel() { g_bcount = 0; g_bgen = 0; }

__global__ void final_fc_kernel(const float* __restrict__ h1hist, const float* __restrict__ fcW,
                                const float* __restrict__ fcb, float* __restrict__ out) {
    int t = blockIdx.y;
    int l = blockIdx.x * 256 + threadIdx.x;
    int b = l >> 6, n = l & 63;
    const float4* h4 = (const float4*)(h1hist + ((size_t)t * BB + b) * HH);
    const float4* w4 = (const float4*)(fcW + (size_t)n * HH);
    float acc = fcb[n];
#pragma unroll 8
    for (int k = 0; k < HH / 4; k++) {
        float4 a = h4[k], w = w4[k];
        acc += a.x * w.x + a.y * w.y + a.z * w.z + a.w * w.w;
    }
    out[((size_t)b * FUT + t) * FF + n] = acc;
}

// ---------------- host ----------------
extern "C" void kernel_launch(void* const* d_in, const int* in_sizes, int n_in,
                              void* d_out, int out_size) {
    const float* in_seq = (const float*)d_in[0];
    const float* eWih0  = (const float*)d_in[1];
    const float* eWhh0  = (const float*)d_in[2];
    const float* ebih0  = (const float*)d_in[3];
    const float* ebhh0  = (const float*)d_in[4];
    const float* eWih1  = (const float*)d_in[5];
    const float* eWhh1  = (const float*)d_in[6];
    const float* ebih1  = (const float*)d_in[7];
    const float* ebhh1  = (const float*)d_in[8];
    const float* dWih0  = (const float*)d_in[9];
    const float* dWhh0  = (const float*)d_in[10];
    const float* dbih0  = (const float*)d_in[11];
    const float* dbhh0  = (const float*)d_in[12];
    const float* dWih1  = (const float*)d_in[13];
    const float* dWhh1  = (const float*)d_in[14];
    const float* dbih1  = (const float*)d_in[15];
    const float* dbhh1  = (const float*)d_in[16];
    const float* fcW    = (const float*)d_in[17];
    const float* fcb    = (const float*)d_in[18];
    float* out = (float*)d_out;

    static int s_attr_done = 0;
    if (!s_attr_done) {
        cudaFuncSetAttribute(enc_kernel, cudaFuncAttributeMaxDynamicSharedMemorySize, ENC_SMEM);
        cudaFuncSetAttribute(dec_kernel, cudaFuncAttributeMaxDynamicSharedMemorySize, DEC_SMEM);
        s_attr_done = 1;
    }

    float4 *pWeih0, *pWehh0, *pWeih1, *pWehh1, *pWdih0, *pWdhh0, *pWdih1, *pWdhh1, *pWd0c;
    float4 *pbE0, *pbE1, *pbD0, *pbD1, *pbD0c;
    float *y0, *h1hist, *zerobuf, *c0, *c1, *h1A, *h1B, *h0A, *h0B;
    cudaGetSymbolAddress((void**)&y0,      g_y0);
    cudaGetSymbolAddress((void**)&h1hist,  g_h1hist);
    cudaGetSymbolAddress((void**)&zerobuf, g_zero);
    cudaGetSymbolAddress((void**)&c0,      g_c0);
    cudaGetSymbolAddress((void**)&c1,      g_c1);
    cudaGetSymbolAddress((void**)&h1A,     g_h1A);
    cudaGetSymbolAddress((void**)&h1B,     g_h1B);
    cudaGetSymbolAddress((void**)&h0A,     g_h0A);
    cudaGetSymbolAddress((void**)&h0B,     g_h0B);
    cudaGetSymbolAddress((void**)&pWeih0,  g_pW_enc_ih0);
    cudaGetSymbolAddress((void**)&pWehh0,  g_pW_enc_hh0);
    cudaGetSymbolAddress((void**)&pWeih1,  g_pW_enc_ih1);
    cudaGetSymbolAddress((void**)&pWehh1,  g_pW_enc_hh1);
    cudaGetSymbolAddress((void**)&pWdih0,  g_pW_dec_ih0);
    cudaGetSymbolAddress((void**)&pWdhh0,  g_pW_dec_hh0);
    cudaGetSymbolAddress((void**)&pWdih1,  g_pW_dec_ih1);
    cudaGetSymbolAddress((void**)&pWdhh1,  g_pW_dec_hh1);
    cudaGetSymbolAddress((void**)&pWd0c,   g_pW_dec0c);
    cudaGetSymbolAddress((void**)&pbE0,    g_pb_enc0);
    cudaGetSymbolAddress((void**)&pbE1,    g_pb_enc1);
    cudaGetSymbolAddress((void**)&pbD0,    g_pb_dec0);
    cudaGetSymbolAddress((void**)&pbD1,    g_pb_dec1);
    cudaGetSymbolAddress((void**)&pbD0c,   g_pb_dec0c);

    // Launch order matters: ncu capture is (-s 5 -c 1) -> launch index 5 = enc_kernel.
    // [0] pack_all
    {
        dim3 grid(1024, 9);
        pack_all_kernel<<<grid, 256>>>(
            eWih0, eWhh0, eWih1, eWhh1, dWih0, dWhh0, dWih1, dWhh1,
            pWeih0, pWehh0, pWeih1, pWehh1, pWdih0, pWdhh0, pWdih1, pWdhh1,
            ebih0, ebhh0, ebih1, ebhh1, dbih0, dbhh0, dbih1, dbhh1,
            pbE0, pbE1, pbD0, pbD1);
    }
    // [1] combine decoder cell0 weights with FC
    combine_dec0_kernel<<<(HH * HH + 255) / 256, 256>>>(pWdih0, fcW, pbD0, fcb, pWd0c, pbD0c);
    // [2] init zero buffer + barrier state
    init_kernel<<<(BH + 255) / 256, 256>>>(zerobuf);
    // [3],[4] padding so enc is launch 5
    nop_kernel<<<1, 1>>>();
    nop_kernel<<<1, 1>>>();

    // [5] persistent encoder
    enc_kernel<<<NBLK, NTHR, ENC_SMEM>>>(
        in_seq, pWeih0, pWehh0, pWeih1, pWehh1, pbE0, pbE1,
        zerobuf, y0, h1A, h1B, c0, c1);

    // [6] reset barrier
    reset_bar_kernel<<<1, 1>>>();

    // [7] persistent decoder
    dec_kernel<<<NBLK, NTHR, DEC_SMEM>>>(
        in_seq, pWdih0, pWd0c, pWdhh0, pWdih1, pWdhh1,
        pbD0, pbD0c, pbD1,
        y0 + (size_t)(TT - 1) * BH,
        h1A,
        c0, c1, h0A, h0B, h1hist);

    // [8] batched final FC
    {
        dim3 grid(16, FUT);
        final_fc_kernel<<<grid, 256>>>(h1hist, fcW, fcb, out);
    }
}